// round 1
// baseline (speedup 1.0000x reference)
#include <cuda_runtime.h>
#include <cuda_bf16.h>
#include <cstdint>

#define NVERT   16384
#define QCOLS   4096                 // columns per quarter
#define NUNITS  32768                // 8192 row-pairs * 4 column-quarters
#define BLOCK   1024
#define GRID    148
#define SMEM_BYTES (3 * NVERT * sizeof(float))   // 196608 B

// Deterministic partial sums: y4[q][row][comp]
__device__ float g_y4[4 * NVERT * 3];

__global__ void zero_out_kernel(float* out) {
    out[0] = 0.0f;
}

__global__ void __launch_bounds__(BLOCK, 1)
lap_main_kernel(const float* __restrict__ L, const float* __restrict__ x) {
    extern __shared__ float sx[];   // SoA: [3][NVERT]

    // Stage x into shared memory (coalesced global read, SoA scatter)
    for (int k = threadIdx.x; k < NVERT * 3; k += BLOCK) {
        float v = x[k];
        int vert = k / 3;
        int c    = k - vert * 3;
        sx[c * NVERT + vert] = v;
    }
    __syncthreads();

    const int lane = threadIdx.x & 31;
    const int gw   = blockIdx.x * (BLOCK / 32) + (threadIdx.x >> 5);
    const int nw   = gridDim.x * (BLOCK / 32);

    for (int u = gw; u < NUNITS; u += nw) {
        const int p = u >> 2;        // row pair index -> rows 2p, 2p+1
        const int q = u & 3;         // column quarter

        const float4* __restrict__ r0 =
            (const float4*)(L + (size_t)(2 * p) * NVERT + q * QCOLS);
        const float4* __restrict__ r1 = r0 + (NVERT / 4);

        const float4* __restrict__ xs0 = (const float4*)(sx + 0 * NVERT + q * QCOLS);
        const float4* __restrict__ xs1 = (const float4*)(sx + 1 * NVERT + q * QCOLS);
        const float4* __restrict__ xs2 = (const float4*)(sx + 2 * NVERT + q * QCOLS);

        float a00 = 0.f, a01 = 0.f, a02 = 0.f;
        float a10 = 0.f, a11 = 0.f, a12 = 0.f;

        #pragma unroll 4
        for (int i = lane; i < QCOLS / 4; i += 32) {
            float4 l0 = __ldcs(r0 + i);   // streaming: L has zero reuse
            float4 l1 = __ldcs(r1 + i);
            float4 v0 = xs0[i];
            float4 v1 = xs1[i];
            float4 v2 = xs2[i];

            a00 += l0.x * v0.x + l0.y * v0.y + l0.z * v0.z + l0.w * v0.w;
            a01 += l0.x * v1.x + l0.y * v1.y + l0.z * v1.z + l0.w * v1.w;
            a02 += l0.x * v2.x + l0.y * v2.y + l0.z * v2.z + l0.w * v2.w;
            a10 += l1.x * v0.x + l1.y * v0.y + l1.z * v0.z + l1.w * v0.w;
            a11 += l1.x * v1.x + l1.y * v1.y + l1.z * v1.z + l1.w * v1.w;
            a12 += l1.x * v2.x + l1.y * v2.y + l1.z * v2.z + l1.w * v2.w;
        }

        // Butterfly warp reduction of all 6 accumulators (result in every lane)
        #pragma unroll
        for (int off = 16; off > 0; off >>= 1) {
            a00 += __shfl_xor_sync(0xFFFFFFFFu, a00, off);
            a01 += __shfl_xor_sync(0xFFFFFFFFu, a01, off);
            a02 += __shfl_xor_sync(0xFFFFFFFFu, a02, off);
            a10 += __shfl_xor_sync(0xFFFFFFFFu, a10, off);
            a11 += __shfl_xor_sync(0xFFFFFFFFu, a11, off);
            a12 += __shfl_xor_sync(0xFFFFFFFFu, a12, off);
        }

        if (lane < 6) {
            float v;
            switch (lane) {
                case 0: v = a00; break;
                case 1: v = a01; break;
                case 2: v = a02; break;
                case 3: v = a10; break;
                case 4: v = a11; break;
                default: v = a12; break;
            }
            const int row = 2 * p + (lane >= 3 ? 1 : 0);
            const int c   = (lane >= 3) ? (lane - 3) : lane;
            g_y4[(q * NVERT + row) * 3 + c] = v;
        }
    }
}

__global__ void pass2_kernel(float* __restrict__ out) {
    __shared__ float red[32];
    float s = 0.f;
    const int stride = gridDim.x * blockDim.x;
    for (int idx = blockIdx.x * blockDim.x + threadIdx.x; idx < NVERT * 3; idx += stride) {
        float v = g_y4[idx]
                + g_y4[idx + 1 * NVERT * 3]
                + g_y4[idx + 2 * NVERT * 3]
                + g_y4[idx + 3 * NVERT * 3];
        s += v * v;
    }
    // warp reduce
    #pragma unroll
    for (int off = 16; off > 0; off >>= 1)
        s += __shfl_xor_sync(0xFFFFFFFFu, s, off);
    const int lane = threadIdx.x & 31;
    const int wid  = threadIdx.x >> 5;
    if (lane == 0) red[wid] = s;
    __syncthreads();
    if (wid == 0) {
        int nwarps = blockDim.x >> 5;
        float t = (lane < nwarps) ? red[lane] : 0.f;
        #pragma unroll
        for (int off = 16; off > 0; off >>= 1)
            t += __shfl_xor_sync(0xFFFFFFFFu, t, off);
        if (lane == 0) atomicAdd(out, t);
    }
}

extern "C" void kernel_launch(void* const* d_in, const int* in_sizes, int n_in,
                              void* d_out, int out_size) {
    // Identify inputs by element count: x has NVERT*3, L has NVERT*NVERT.
    const float* x = (const float*)d_in[0];
    const float* L = (const float*)d_in[1];
    if (in_sizes[0] != NVERT * 3) {
        x = (const float*)d_in[1];
        L = (const float*)d_in[0];
    }
    float* out = (float*)d_out;

    // Opt in to 192 KB dynamic shared memory (idempotent, capture-safe).
    cudaFuncSetAttribute(lap_main_kernel,
                         cudaFuncAttributeMaxDynamicSharedMemorySize,
                         (int)SMEM_BYTES);

    zero_out_kernel<<<1, 1>>>(out);
    lap_main_kernel<<<GRID, BLOCK, SMEM_BYTES>>>(L, x);
    pass2_kernel<<<48, 256>>>(out);
}

// round 2
// speedup vs baseline: 1.0097x; 1.0097x over previous
#include <cuda_runtime.h>
#include <cuda_bf16.h>
#include <cstdint>

#define NVERT   16384
#define QCOLS   4096                 // columns per quarter
#define NUNITS  32768                // 8192 row-pairs * 4 column-quarters
#define BLOCK   1024
#define GRID    148
#define NWARPS  (GRID * (BLOCK / 32))
#define SMEM_BYTES (3 * NVERT * sizeof(float))   // 196608 B

// Deterministic partial sums: y4[q][row][comp]
__device__ float g_y4[4 * NVERT * 3];
// Work-stealing state (self-resetting: last warp restores to 0 for graph replays)
__device__ unsigned int g_ticket = 0;
__device__ unsigned int g_done   = 0;

__global__ void __launch_bounds__(BLOCK, 1)
lap_main_kernel(const float* __restrict__ L, const float* __restrict__ x,
                float* __restrict__ out) {
    extern __shared__ float sx[];   // SoA: [3][NVERT]

    // Zero the output once (pass2 is a later launch; ordering guaranteed).
    if (blockIdx.x == 0 && threadIdx.x == 0) out[0] = 0.0f;

    // Stage x into shared memory: SoA, per-vertex (no divides, 16 iterations)
    for (int vert = threadIdx.x; vert < NVERT; vert += BLOCK) {
        float a = x[3 * vert + 0];
        float b = x[3 * vert + 1];
        float c = x[3 * vert + 2];
        sx[0 * NVERT + vert] = a;
        sx[1 * NVERT + vert] = b;
        sx[2 * NVERT + vert] = c;
    }
    __syncthreads();

    const int lane = threadIdx.x & 31;

    for (;;) {
        unsigned int u;
        if (lane == 0) u = atomicAdd(&g_ticket, 1u);
        u = __shfl_sync(0xFFFFFFFFu, u, 0);
        if (u >= NUNITS) break;

        const int p = (int)(u >> 2);   // row pair index -> rows 2p, 2p+1
        const int q = (int)(u & 3);    // column quarter

        const float4* __restrict__ r0 =
            (const float4*)(L + (size_t)(2 * p) * NVERT + q * QCOLS);
        const float4* __restrict__ r1 = r0 + (NVERT / 4);

        const float4* __restrict__ xs0 = (const float4*)(sx + 0 * NVERT + q * QCOLS);
        const float4* __restrict__ xs1 = (const float4*)(sx + 1 * NVERT + q * QCOLS);
        const float4* __restrict__ xs2 = (const float4*)(sx + 2 * NVERT + q * QCOLS);

        float a00 = 0.f, a01 = 0.f, a02 = 0.f;
        float a10 = 0.f, a11 = 0.f, a12 = 0.f;

        #pragma unroll 4
        for (int i = lane; i < QCOLS / 4; i += 32) {
            float4 l0 = __ldcs(r0 + i);   // streaming: L has zero reuse
            float4 l1 = __ldcs(r1 + i);
            float4 v0 = xs0[i];
            float4 v1 = xs1[i];
            float4 v2 = xs2[i];

            a00 += l0.x * v0.x + l0.y * v0.y + l0.z * v0.z + l0.w * v0.w;
            a01 += l0.x * v1.x + l0.y * v1.y + l0.z * v1.z + l0.w * v1.w;
            a02 += l0.x * v2.x + l0.y * v2.y + l0.z * v2.z + l0.w * v2.w;
            a10 += l1.x * v0.x + l1.y * v0.y + l1.z * v0.z + l1.w * v0.w;
            a11 += l1.x * v1.x + l1.y * v1.y + l1.z * v1.z + l1.w * v1.w;
            a12 += l1.x * v2.x + l1.y * v2.y + l1.z * v2.z + l1.w * v2.w;
        }

        // Butterfly warp reduction of all 6 accumulators
        #pragma unroll
        for (int off = 16; off > 0; off >>= 1) {
            a00 += __shfl_xor_sync(0xFFFFFFFFu, a00, off);
            a01 += __shfl_xor_sync(0xFFFFFFFFu, a01, off);
            a02 += __shfl_xor_sync(0xFFFFFFFFu, a02, off);
            a10 += __shfl_xor_sync(0xFFFFFFFFu, a10, off);
            a11 += __shfl_xor_sync(0xFFFFFFFFu, a11, off);
            a12 += __shfl_xor_sync(0xFFFFFFFFu, a12, off);
        }

        if (lane < 6) {
            float v;
            switch (lane) {
                case 0: v = a00; break;
                case 1: v = a01; break;
                case 2: v = a02; break;
                case 3: v = a10; break;
                case 4: v = a11; break;
                default: v = a12; break;
            }
            const int row = 2 * p + (lane >= 3 ? 1 : 0);
            const int c   = (lane >= 3) ? (lane - 3) : lane;
            g_y4[(q * NVERT + row) * 3 + c] = v;
        }
    }

    // Self-reset of work-stealing counters: last warp to finish restores 0s
    // so the next graph replay starts clean. All other warps have already
    // performed their final g_ticket atomicAdd before incrementing g_done.
    if (lane == 0) {
        __threadfence();
        unsigned int d = atomicAdd(&g_done, 1u);
        if (d == NWARPS - 1) {
            g_ticket = 0;
            g_done   = 0;
            __threadfence();
        }
    }
}

__global__ void pass2_kernel(float* __restrict__ out) {
    __shared__ float red[32];
    float s = 0.f;
    const int stride = gridDim.x * blockDim.x;
    for (int idx = blockIdx.x * blockDim.x + threadIdx.x; idx < NVERT * 3; idx += stride) {
        float v = g_y4[idx]
                + g_y4[idx + 1 * NVERT * 3]
                + g_y4[idx + 2 * NVERT * 3]
                + g_y4[idx + 3 * NVERT * 3];
        s += v * v;
    }
    #pragma unroll
    for (int off = 16; off > 0; off >>= 1)
        s += __shfl_xor_sync(0xFFFFFFFFu, s, off);
    const int lane = threadIdx.x & 31;
    const int wid  = threadIdx.x >> 5;
    if (lane == 0) red[wid] = s;
    __syncthreads();
    if (wid == 0) {
        int nwarps = blockDim.x >> 5;
        float t = (lane < nwarps) ? red[lane] : 0.f;
        #pragma unroll
        for (int off = 16; off > 0; off >>= 1)
            t += __shfl_xor_sync(0xFFFFFFFFu, t, off);
        if (lane == 0) atomicAdd(out, t);
    }
}

extern "C" void kernel_launch(void* const* d_in, const int* in_sizes, int n_in,
                              void* d_out, int out_size) {
    // Identify inputs by element count: x has NVERT*3, L has NVERT*NVERT.
    const float* x = (const float*)d_in[0];
    const float* L = (const float*)d_in[1];
    if (in_sizes[0] != NVERT * 3) {
        x = (const float*)d_in[1];
        L = (const float*)d_in[0];
    }
    float* out = (float*)d_out;

    // Opt in to 192 KB dynamic shared memory (idempotent, capture-safe).
    cudaFuncSetAttribute(lap_main_kernel,
                         cudaFuncAttributeMaxDynamicSharedMemorySize,
                         (int)SMEM_BYTES);

    lap_main_kernel<<<GRID, BLOCK, SMEM_BYTES>>>(L, x, out);
    pass2_kernel<<<48, 256>>>(out);
}